// round 3
// baseline (speedup 1.0000x reference)
#include <cuda_runtime.h>

// ---------------------------------------------------------------------------
// CausalVAE2: B=262144, D=64, HID=256
// out layout: [x_out B*64][mu B*64][log_var B*64][y_recon B*128]
// ---------------------------------------------------------------------------

#define BATCH 262144
#define DD 64
#define HID 256

// Scratch (device globals — allocation in kernel_launch is forbidden)
__device__ float g_ey[(size_t)BATCH * DD];   // 64 MB: eps_y
__device__ int   g_mask[DD * DD];            // B_mask as 0/1 int

// ---- packed f32x2 helpers (Blackwell packed-FP32 datapath) ----------------
static __device__ __forceinline__ unsigned long long pk2(float lo, float hi) {
    unsigned long long r;
    asm("mov.b64 %0, {%1, %2};" : "=l"(r) : "f"(lo), "f"(hi));
    return r;
}
static __device__ __forceinline__ unsigned long long ffma2(unsigned long long a,
                                                           unsigned long long b,
                                                           unsigned long long c) {
    unsigned long long d;
    asm("fma.rn.f32x2 %0, %1, %2, %3;" : "=l"(d) : "l"(a), "l"(b), "l"(c));
    return d;
}
static __device__ __forceinline__ void upk2(unsigned long long v, float& lo, float& hi) {
    asm("mov.b64 {%0, %1}, %2;" : "=f"(lo), "=f"(hi) : "l"(v));
}

extern __shared__ float smem[];

// ---------------------------------------------------------------------------
// Mask decode: B_mask is jnp.bool_; harness dtype mapping is ambiguous.
// Detect layout from the 4096-element logical mask:
//   int32  : all bytes at idx%4!=0 are zero (values 0/1 in low byte)
//   uint8  : bytes 0/1 everywhere, some nonzero at idx%4!=0
//   float32: 1.0f contains bytes 0x80/0x3F (byte > 1 appears)
// ---------------------------------------------------------------------------
__global__ void mask_expand_kernel(const unsigned char* __restrict__ mb) {
    __shared__ int flags[2];
    __shared__ int s_mode;
    int tid = threadIdx.x;
    if (tid < 2) flags[tid] = 0;
    __syncthreads();
    for (int idx = tid; idx < DD * DD; idx += blockDim.x) {
        unsigned char b = mb[idx];
        if ((idx & 3) != 0 && b != 0) {
            atomicOr(&flags[1], 1);
            if (b > 1) atomicOr(&flags[0], 1);
        }
    }
    __syncthreads();
    if (tid == 0) s_mode = flags[0] ? 2 : (flags[1] ? 1 : 0);
    __syncthreads();
    int mode = s_mode;
    for (int idx = tid; idx < DD * DD; idx += blockDim.x) {
        int v;
        if (mode == 2)      v = (((const float*)mb)[idx] != 0.0f);
        else if (mode == 1) v = (mb[idx] != 0);
        else                v = (((const int*)mb)[idx] != 0);
        g_mask[idx] = v;
    }
}

// ---------------------------------------------------------------------------
// Zero the right half of y_recon (cols 64..127), as float4.
// ---------------------------------------------------------------------------
__global__ void zero_yr_kernel(float4* __restrict__ yr) {
    size_t idx = (size_t)blockIdx.x * blockDim.x + threadIdx.x;  // B*16 float4s
    size_t row = idx >> 4;
    int c4 = (int)(idx & 15);
    yr[row * 32 + 16 + c4] = make_float4(0.f, 0.f, 0.f, 0.f);
}

// ---------------------------------------------------------------------------
// Fused encoder: per 64-row tile
//   h  = relu(x @ enc1_w + enc1_b)          (kept in smem, never hits HBM)
//   z  = h @ enc3_w + enc3_b
//   mu = z[:, :64]; lv = z[:, 64:]
//   eps_y = mu + exp(lv/2)*eps   -> g_ey
// smem: region0 32768 floats (W1[64][256]+xT in upper half, then W2[256][128])
//       hbuf 16384 floats, b1 256, b2 128   => 198,144 bytes
// ---------------------------------------------------------------------------
__global__ __launch_bounds__(256, 1) void enc_fused_kernel(const float* __restrict__ x,
                                                           const float* __restrict__ eps,
                                                           const float* __restrict__ w1g,
                                                           const float* __restrict__ b1g,
                                                           const float* __restrict__ w2g,
                                                           const float* __restrict__ b2g,
                                                           float* __restrict__ outMu,
                                                           float* __restrict__ outLv) {
    float* sR0  = smem;                  // 32768 floats
    float* sW1  = sR0;                   // [64][256]
    float* sXT  = sR0 + DD * HID;        // [64][65] transposed x tile
    float* hbuf = sR0 + 32768;           // [64][256]
    float* sB1  = hbuf + DD * HID;       // 256
    float* sB2  = sB1 + HID;             // 128
    int tid = threadIdx.x;
    int row0 = blockIdx.x * 64;

    // ---- stage W1, b1, b2, xT ----
    {
        const float4* w4 = (const float4*)w1g;
        float4* sW4 = (float4*)sW1;
#pragma unroll
        for (int t = 0; t < 16; t++) sW4[tid + 256 * t] = w4[tid + 256 * t];
        sB1[tid] = b1g[tid];
        if (tid < 128) sB2[tid] = b2g[tid];
        for (int idx = tid; idx < 64 * DD; idx += 256) {
            int r = idx >> 6, k = idx & 63;
            sXT[k * 65 + r] = x[(size_t)(row0 + r) * DD + k];
        }
    }
    __syncthreads();

    int cg = tid & 31, rg = tid >> 5;

    // ---- GEMM1: h[64][256] = relu(x@W1+b1) ----
    {
        int c0 = cg * 8, r0 = rg * 8;
        unsigned long long acc[8][4];
#pragma unroll
        for (int r = 0; r < 8; r++)
#pragma unroll
            for (int j = 0; j < 4; j++) acc[r][j] = 0ull;

        for (int k = 0; k < DD; k++) {
            float4 wa = *(const float4*)&sW1[k * HID + c0];
            float4 wb = *(const float4*)&sW1[k * HID + c0 + 4];
            unsigned long long w2[4];
            w2[0] = pk2(wa.x, wa.y); w2[1] = pk2(wa.z, wa.w);
            w2[2] = pk2(wb.x, wb.y); w2[3] = pk2(wb.z, wb.w);
#pragma unroll
            for (int r = 0; r < 8; r++) {
                float e = sXT[k * 65 + r0 + r];
                unsigned long long e2 = pk2(e, e);
#pragma unroll
                for (int j = 0; j < 4; j++) acc[r][j] = ffma2(e2, w2[j], acc[r][j]);
            }
        }
        __syncthreads();  // everyone done READING sW1/sXT before hbuf write is fine;
                          // hbuf is a distinct region, but we need all reads of sR0
                          // done before GEMM2's W2 overwrite below — sync here anchors that.
#pragma unroll
        for (int r = 0; r < 8; r++) {
            float v[8];
#pragma unroll
            for (int j = 0; j < 4; j++) upk2(acc[r][j], v[2 * j], v[2 * j + 1]);
            float4 o1, o2;
            o1.x = fmaxf(v[0] + sB1[c0 + 0], 0.f);
            o1.y = fmaxf(v[1] + sB1[c0 + 1], 0.f);
            o1.z = fmaxf(v[2] + sB1[c0 + 2], 0.f);
            o1.w = fmaxf(v[3] + sB1[c0 + 3], 0.f);
            o2.x = fmaxf(v[4] + sB1[c0 + 4], 0.f);
            o2.y = fmaxf(v[5] + sB1[c0 + 5], 0.f);
            o2.z = fmaxf(v[6] + sB1[c0 + 6], 0.f);
            o2.w = fmaxf(v[7] + sB1[c0 + 7], 0.f);
            *(float4*)&hbuf[(r0 + r) * HID + c0] = o1;
            *(float4*)&hbuf[(r0 + r) * HID + c0 + 4] = o2;
        }
    }

    // ---- overwrite region0 with W2 [256][128] ----
    {
        const float4* w4 = (const float4*)w2g;
        float4* sW4 = (float4*)sR0;
#pragma unroll
        for (int t = 0; t < 32; t++) sW4[tid + 256 * t] = w4[tid + 256 * t];
    }
    __syncthreads();

    // ---- GEMM2: z[64][128] = h@W2+b2; epilogue mu/lv/eps_y ----
    {
        int c0 = cg * 4, r0 = rg * 8;
        unsigned long long acc[8][2];
#pragma unroll
        for (int r = 0; r < 8; r++) { acc[r][0] = 0ull; acc[r][1] = 0ull; }

        for (int k = 0; k < HID; k++) {
            float4 wa = *(const float4*)&sR0[k * 128 + c0];
            unsigned long long w20 = pk2(wa.x, wa.y), w21 = pk2(wa.z, wa.w);
#pragma unroll
            for (int r = 0; r < 8; r++) {
                float e = hbuf[(r0 + r) * HID + k];   // warp-broadcast
                unsigned long long e2 = pk2(e, e);
                acc[r][0] = ffma2(e2, w20, acc[r][0]);
                acc[r][1] = ffma2(e2, w21, acc[r][1]);
            }
        }
        __syncthreads();          // done reading hbuf; reuse as zbuf [64][128]
        float* zb = hbuf;
#pragma unroll
        for (int r = 0; r < 8; r++) {
            float v[4];
            upk2(acc[r][0], v[0], v[1]);
            upk2(acc[r][1], v[2], v[3]);
            float4 o;
            o.x = v[0] + sB2[c0 + 0];
            o.y = v[1] + sB2[c0 + 1];
            o.z = v[2] + sB2[c0 + 2];
            o.w = v[3] + sB2[c0 + 3];
            *(float4*)&zb[(r0 + r) * 128 + c0] = o;
        }
        __syncthreads();
        for (int idx = tid; idx < 64 * 64; idx += 256) {
            int r = idx >> 6, c = idx & 63;
            size_t row = (size_t)row0 + r;
            float mu = zb[r * 128 + c];
            float lv = zb[r * 128 + 64 + c];
            float e = eps[row * DD + c];
            float ey = mu + expf(lv * 0.5f) * e;
            outMu[row * DD + c] = mu;
            outLv[row * DD + c] = lv;
            g_ey[row * DD + c] = ey;
        }
    }
}

// ---------------------------------------------------------------------------
// decoder: for each i: out[:,i] = relu(eps_y @ (dec1_w[i]*mask) + dec1_b[i]) . dec3_w[i] + dec3_b[i]
// Block: fixed i, masked W1[i] pinned in smem (64KB), loops tiles of 64 rows.
// grid = (64, 8).
// ---------------------------------------------------------------------------
__global__ __launch_bounds__(256, 2) void dec_kernel(const float* __restrict__ w1g,
                                                     const float* __restrict__ b1g,
                                                     const float* __restrict__ w3g,
                                                     const float* __restrict__ b3g,
                                                     float* __restrict__ outX,
                                                     float* __restrict__ outYr) {
    float* sW  = smem;                // DD*HID
    float* sE  = sW + DD * HID;       // DD*65
    float* sw3 = sE + DD * 65;        // HID
    float* sb1 = sw3 + HID;           // HID
    int tid = threadIdx.x;
    int i = blockIdx.x;

    const float4* w4 = (const float4*)(w1g + (size_t)i * DD * HID);
    float4* sW4 = (float4*)sW;
#pragma unroll
    for (int t = 0; t < 16; t++) {
        int f = tid + 256 * t;
        int k = f >> 6;  // f*4/256
        float m = (float)g_mask[k * DD + i];
        float4 v = w4[f];
        v.x *= m; v.y *= m; v.z *= m; v.w *= m;
        sW4[f] = v;
    }
    sw3[tid] = w3g[(size_t)i * HID + tid];
    sb1[tid] = b1g[(size_t)i * HID + tid];
    float b3s = b3g[i];

    int cg = tid & 31, rg = tid >> 5;
    int c0 = cg * 8, r0 = rg * 8;
    int lane = cg;

    const int rowsPerBlk = BATCH / 8;
    int rbase = blockIdx.y * rowsPerBlk;

    for (int t = 0; t < rowsPerBlk / 64; t++) {
        int row0 = rbase + t * 64;
        __syncthreads();  // also covers initial W/sw3/sb1 staging on t==0
        for (int idx = tid; idx < 64 * DD; idx += 256) {
            int r = idx >> 6, k = idx & 63;
            sE[k * 65 + r] = g_ey[(size_t)(row0 + r) * DD + k];
        }
        __syncthreads();

        unsigned long long acc[8][4];
#pragma unroll
        for (int r = 0; r < 8; r++)
#pragma unroll
            for (int j = 0; j < 4; j++) acc[r][j] = 0ull;

        for (int k = 0; k < DD; k++) {
            float4 wa = *(const float4*)&sW[k * HID + c0];
            float4 wb = *(const float4*)&sW[k * HID + c0 + 4];
            unsigned long long w2[4];
            w2[0] = pk2(wa.x, wa.y); w2[1] = pk2(wa.z, wa.w);
            w2[2] = pk2(wb.x, wb.y); w2[3] = pk2(wb.z, wb.w);
#pragma unroll
            for (int r = 0; r < 8; r++) {
                float e = sE[k * 65 + r0 + r];
                unsigned long long e2 = pk2(e, e);
#pragma unroll
                for (int j = 0; j < 4; j++) acc[r][j] = ffma2(e2, w2[j], acc[r][j]);
            }
        }

        float pr[8];
#pragma unroll
        for (int r = 0; r < 8; r++) {
            float v[8];
#pragma unroll
            for (int j = 0; j < 4; j++) upk2(acc[r][j], v[2 * j], v[2 * j + 1]);
            float s = 0.f;
#pragma unroll
            for (int j = 0; j < 8; j++) {
                float hm = fmaxf(v[j] + sb1[c0 + j], 0.f);
                s += hm * sw3[c0 + j];
            }
            pr[r] = s;
        }
        // butterfly reduce across the 32 lanes of this warp
#pragma unroll
        for (int off = 16; off > 0; off >>= 1)
#pragma unroll
            for (int r = 0; r < 8; r++)
                pr[r] += __shfl_xor_sync(0xFFFFFFFFu, pr[r], off);

        if (lane < 8) {
            float myv = pr[0];
#pragma unroll
            for (int r = 1; r < 8; r++)
                if (lane == r) myv = pr[r];
            size_t row = (size_t)row0 + r0 + lane;
            float o = myv + b3s;
            outX[row * DD + i] = o;
            outYr[row * 128 + i] = o;
        }
    }
}

// ---------------------------------------------------------------------------
extern "C" void kernel_launch(void* const* d_in, const int* in_sizes, int n_in,
                              void* d_out, int out_size) {
    const float* x      = (const float*)d_in[0];
    const float* eps    = (const float*)d_in[1];
    const float* enc1_w = (const float*)d_in[2];
    const float* enc1_b = (const float*)d_in[3];
    const float* enc3_w = (const float*)d_in[4];
    const float* enc3_b = (const float*)d_in[5];
    const float* dec1_w = (const float*)d_in[6];
    const float* dec1_b = (const float*)d_in[7];
    const float* dec3_w = (const float*)d_in[8];
    const float* dec3_b = (const float*)d_in[9];
    const unsigned char* bmask = (const unsigned char*)d_in[10];
    (void)n_in; (void)in_sizes; (void)out_size;

    float* out   = (float*)d_out;
    float* outX  = out;
    float* outMu = out + (size_t)BATCH * DD;
    float* outLv = out + (size_t)2 * BATCH * DD;
    float* outYr = out + (size_t)3 * BATCH * DD;

    size_t sEnc = (size_t)(32768 + DD * HID + HID + 128) * sizeof(float);   // 198,144
    size_t sDec = (size_t)(DD * HID + DD * 65 + 2 * HID) * sizeof(float);   //  84,224
    cudaFuncSetAttribute(enc_fused_kernel, cudaFuncAttributeMaxDynamicSharedMemorySize, (int)sEnc);
    cudaFuncSetAttribute(dec_kernel,       cudaFuncAttributeMaxDynamicSharedMemorySize, (int)sDec);

    mask_expand_kernel<<<1, 256>>>(bmask);
    zero_yr_kernel<<<(BATCH * 16) / 256, 256>>>((float4*)outYr);
    enc_fused_kernel<<<BATCH / 64, 256, sEnc>>>(x, eps, enc1_w, enc1_b,
                                                enc3_w, enc3_b, outMu, outLv);
    dec_kernel<<<dim3(64, 8), 256, sDec>>>(dec1_w, dec1_b, dec3_w, dec3_b, outX, outYr);
}

// round 5
// speedup vs baseline: 2.8566x; 2.8566x over previous
#include <cuda_runtime.h>
#include <cuda_bf16.h>
#include <cstdint>

// ---------------------------------------------------------------------------
// CausalVAE2: B=262144, D=64, HID=256
// out layout: [x_out B*64][mu B*64][log_var B*64][y_recon B*128]
// Decoder: warp-level mma.sync bf16 split-precision (baseline PTX; tcgen05
// rejected because harness PTX target is sm_100 without the 'a' feature set).
// ---------------------------------------------------------------------------

#define BATCH 262144
#define DD 64
#define HID 256
#define NTILES (BATCH / 128)          // 2048 row tiles of 128

// Scratch (device globals — no allocation allowed anywhere)
// A' tiles: [tile][row 0..127][k 0..63 hi | 64..127 lo] bf16 row-major (32KB/tile)
__device__ __align__(16) unsigned char g_abf[(size_t)NTILES * 32768]; // 64MB
// W' per i: [n 0..255][k 0..63 hi | 64..127 lo] bf16 row-major (64KB/i)
__device__ __align__(16) unsigned char g_wbf[(size_t)DD * 65536];     // 4MB
__device__ int g_mask[DD * DD];

// ---- packed f32x2 helpers (encoder) ---------------------------------------
static __device__ __forceinline__ unsigned long long pk2(float lo, float hi) {
    unsigned long long r;
    asm("mov.b64 %0, {%1, %2};" : "=l"(r) : "f"(lo), "f"(hi));
    return r;
}
static __device__ __forceinline__ unsigned long long ffma2(unsigned long long a,
                                                           unsigned long long b,
                                                           unsigned long long c) {
    unsigned long long d;
    asm("fma.rn.f32x2 %0, %1, %2, %3;" : "=l"(d) : "l"(a), "l"(b), "l"(c));
    return d;
}
static __device__ __forceinline__ void upk2(unsigned long long v, float& lo, float& hi) {
    asm("mov.b64 {%0, %1}, %2;" : "=f"(lo), "=f"(hi) : "l"(v));
}

// ---- baseline tensor-core primitives --------------------------------------
static __device__ __forceinline__ uint32_t smem_u32(const void* p) {
    uint32_t a;
    asm("{ .reg .u64 t; cvta.to.shared.u64 t, %1; cvt.u32.u64 %0, t; }" : "=r"(a) : "l"(p));
    return a;
}
static __device__ __forceinline__ void ldsm_x4(uint32_t addr, uint32_t& r0, uint32_t& r1,
                                               uint32_t& r2, uint32_t& r3) {
    asm volatile("ldmatrix.sync.aligned.m8n8.x4.shared.b16 {%0,%1,%2,%3}, [%4];"
                 : "=r"(r0), "=r"(r1), "=r"(r2), "=r"(r3) : "r"(addr));
}
static __device__ __forceinline__ void mma16816(float* d, const uint32_t* a,
                                                uint32_t b0, uint32_t b1) {
    asm volatile("mma.sync.aligned.m16n8k16.row.col.f32.bf16.bf16.f32 "
                 "{%0,%1,%2,%3}, {%4,%5,%6,%7}, {%8,%9}, {%0,%1,%2,%3};"
                 : "+f"(d[0]), "+f"(d[1]), "+f"(d[2]), "+f"(d[3])
                 : "r"(a[0]), "r"(a[1]), "r"(a[2]), "r"(a[3]), "r"(b0), "r"(b1));
}
static __device__ __forceinline__ void cp_async16(uint32_t dst, const void* src) {
    asm volatile("cp.async.cg.shared.global [%0], [%1], 16;" :: "r"(dst), "l"(src));
}
#define CP_COMMIT() asm volatile("cp.async.commit_group;" ::: "memory")
#define CP_WAIT0()  asm volatile("cp.async.wait_group 0;" ::: "memory")

extern __shared__ __align__(1024) char smemraw[];

// ---------------------------------------------------------------------------
// Mask decode (robust to bool delivered as u8 / i32 / f32)
// ---------------------------------------------------------------------------
__global__ void mask_expand_kernel(const unsigned char* __restrict__ mb) {
    __shared__ int flags[2];
    __shared__ int s_mode;
    int tid = threadIdx.x;
    if (tid < 2) flags[tid] = 0;
    __syncthreads();
    for (int idx = tid; idx < DD * DD; idx += blockDim.x) {
        unsigned char b = mb[idx];
        if ((idx & 3) != 0 && b != 0) {
            atomicOr(&flags[1], 1);
            if (b > 1) atomicOr(&flags[0], 1);
        }
    }
    __syncthreads();
    if (tid == 0) s_mode = flags[0] ? 2 : (flags[1] ? 1 : 0);
    __syncthreads();
    int mode = s_mode;
    for (int idx = tid; idx < DD * DD; idx += blockDim.x) {
        int v;
        if (mode == 2)      v = (((const float*)mb)[idx] != 0.0f);
        else if (mode == 1) v = (mb[idx] != 0);
        else                v = (((const int*)mb)[idx] != 0);
        g_mask[idx] = v;
    }
}

// ---------------------------------------------------------------------------
// W-prep: per i, masked dec1_w -> bf16 hi/lo, layout [n][k-hi|k-lo].
// ---------------------------------------------------------------------------
__global__ void wprep_kernel(const float* __restrict__ w1g) {
    int i = blockIdx.x, tid = threadIdx.x;
    unsigned char* wb = g_wbf + (size_t)i * 65536;
    for (int idx = tid; idx < DD * HID; idx += blockDim.x) {
        int k = idx >> 8, n = idx & 255;
        float m = (float)g_mask[k * DD + i];
        float w = w1g[(size_t)i * DD * HID + (size_t)k * HID + n] * m;
        __nv_bfloat16 hi = __float2bfloat16(w);
        __nv_bfloat16 lo = __float2bfloat16(w - __bfloat162float(hi));
        *(__nv_bfloat16*)(wb + n * 256 + k * 2) = hi;
        *(__nv_bfloat16*)(wb + n * 256 + 128 + k * 2) = lo;
    }
}

__global__ void zero_yr_kernel(float4* __restrict__ yr) {
    size_t idx = (size_t)blockIdx.x * blockDim.x + threadIdx.x;
    size_t row = idx >> 4;
    int c4 = (int)(idx & 15);
    yr[row * 32 + 16 + c4] = make_float4(0.f, 0.f, 0.f, 0.f);
}

// ---------------------------------------------------------------------------
// Fused encoder (f32x2). Epilogue emits eps_y as A' bf16 hi/lo tiles.
// ---------------------------------------------------------------------------
__global__ __launch_bounds__(256, 1) void enc_fused_kernel(const float* __restrict__ x,
                                                           const float* __restrict__ eps,
                                                           const float* __restrict__ w1g,
                                                           const float* __restrict__ b1g,
                                                           const float* __restrict__ w2g,
                                                           const float* __restrict__ b2g,
                                                           float* __restrict__ outMu,
                                                           float* __restrict__ outLv) {
    float* smem = (float*)smemraw;
    float* sR0  = smem;                  // 32768 floats
    float* sW1  = sR0;                   // [64][256]
    float* sXT  = sR0 + DD * HID;        // [64][65]
    float* hbuf = sR0 + 32768;           // [64][256]
    float* sB1  = hbuf + DD * HID;       // 256
    float* sB2  = sB1 + HID;             // 128
    int tid = threadIdx.x;
    int row0 = blockIdx.x * 64;

    {
        const float4* w4 = (const float4*)w1g;
        float4* sW4 = (float4*)sW1;
#pragma unroll
        for (int t = 0; t < 16; t++) sW4[tid + 256 * t] = w4[tid + 256 * t];
        sB1[tid] = b1g[tid];
        if (tid < 128) sB2[tid] = b2g[tid];
        for (int idx = tid; idx < 64 * DD; idx += 256) {
            int r = idx >> 6, k = idx & 63;
            sXT[k * 65 + r] = x[(size_t)(row0 + r) * DD + k];
        }
    }
    __syncthreads();

    int cg = tid & 31, rg = tid >> 5;

    // GEMM1: h = relu(x@W1+b1)
    {
        int c0 = cg * 8, r0 = rg * 8;
        unsigned long long acc[8][4];
#pragma unroll
        for (int r = 0; r < 8; r++)
#pragma unroll
            for (int j = 0; j < 4; j++) acc[r][j] = 0ull;
        for (int k = 0; k < DD; k++) {
            float4 wa = *(const float4*)&sW1[k * HID + c0];
            float4 wb = *(const float4*)&sW1[k * HID + c0 + 4];
            unsigned long long w2[4];
            w2[0] = pk2(wa.x, wa.y); w2[1] = pk2(wa.z, wa.w);
            w2[2] = pk2(wb.x, wb.y); w2[3] = pk2(wb.z, wb.w);
#pragma unroll
            for (int r = 0; r < 8; r++) {
                float e = sXT[k * 65 + r0 + r];
                unsigned long long e2 = pk2(e, e);
#pragma unroll
                for (int j = 0; j < 4; j++) acc[r][j] = ffma2(e2, w2[j], acc[r][j]);
            }
        }
        __syncthreads();
#pragma unroll
        for (int r = 0; r < 8; r++) {
            float v[8];
#pragma unroll
            for (int j = 0; j < 4; j++) upk2(acc[r][j], v[2 * j], v[2 * j + 1]);
            float4 o1, o2;
            o1.x = fmaxf(v[0] + sB1[c0 + 0], 0.f);
            o1.y = fmaxf(v[1] + sB1[c0 + 1], 0.f);
            o1.z = fmaxf(v[2] + sB1[c0 + 2], 0.f);
            o1.w = fmaxf(v[3] + sB1[c0 + 3], 0.f);
            o2.x = fmaxf(v[4] + sB1[c0 + 4], 0.f);
            o2.y = fmaxf(v[5] + sB1[c0 + 5], 0.f);
            o2.z = fmaxf(v[6] + sB1[c0 + 6], 0.f);
            o2.w = fmaxf(v[7] + sB1[c0 + 7], 0.f);
            *(float4*)&hbuf[(r0 + r) * HID + c0] = o1;
            *(float4*)&hbuf[(r0 + r) * HID + c0 + 4] = o2;
        }
    }

    // W2 overwrite
    {
        const float4* w4 = (const float4*)w2g;
        float4* sW4 = (float4*)sR0;
#pragma unroll
        for (int t = 0; t < 32; t++) sW4[tid + 256 * t] = w4[tid + 256 * t];
    }
    __syncthreads();

    // GEMM2 + epilogue
    {
        int c0 = cg * 4, r0 = rg * 8;
        unsigned long long acc[8][2];
#pragma unroll
        for (int r = 0; r < 8; r++) { acc[r][0] = 0ull; acc[r][1] = 0ull; }
        for (int k = 0; k < HID; k++) {
            float4 wa = *(const float4*)&sR0[k * 128 + c0];
            unsigned long long w20 = pk2(wa.x, wa.y), w21 = pk2(wa.z, wa.w);
#pragma unroll
            for (int r = 0; r < 8; r++) {
                float e = hbuf[(r0 + r) * HID + k];
                unsigned long long e2 = pk2(e, e);
                acc[r][0] = ffma2(e2, w20, acc[r][0]);
                acc[r][1] = ffma2(e2, w21, acc[r][1]);
            }
        }
        __syncthreads();
        float* zb = hbuf;
#pragma unroll
        for (int r = 0; r < 8; r++) {
            float v[4];
            upk2(acc[r][0], v[0], v[1]);
            upk2(acc[r][1], v[2], v[3]);
            float4 o;
            o.x = v[0] + sB2[c0 + 0];
            o.y = v[1] + sB2[c0 + 1];
            o.z = v[2] + sB2[c0 + 2];
            o.w = v[3] + sB2[c0 + 3];
            *(float4*)&zb[(r0 + r) * 128 + c0] = o;
        }
        __syncthreads();
        for (int idx = tid; idx < 64 * 64; idx += 256) {
            int r = idx >> 6, c = idx & 63;
            int rowAbs = row0 + r;
            float mu = zb[r * 128 + c];
            float lv = zb[r * 128 + 64 + c];
            float e = eps[(size_t)rowAbs * DD + c];
            float ey = mu + expf(lv * 0.5f) * e;
            outMu[(size_t)rowAbs * DD + c] = mu;
            outLv[(size_t)rowAbs * DD + c] = lv;
            __nv_bfloat16 hi = __float2bfloat16(ey);
            __nv_bfloat16 lo = __float2bfloat16(ey - __bfloat162float(hi));
            int tile = rowAbs >> 7, rl = rowAbs & 127;
            unsigned char* tb = g_abf + (size_t)tile * 32768;
            *(__nv_bfloat16*)(tb + rl * 256 + c * 2) = hi;
            *(__nv_bfloat16*)(tb + rl * 256 + 128 + c * 2) = lo;
        }
    }
}

// ---------------------------------------------------------------------------
// Decoder (mma.sync bf16, 3-term split). grid = (64 i, 64 groups of 32 tiles).
// smem: sB1 [0,1KB), sW3 [1KB,2KB), W' @2048 (256 rows x 272B = 69632),
//       A0 @71680 (128 x 272 = 34816), A1 @106496. Total 141312 B.
// Warp w: rows w*16..w*16+15, all 256 cols.
// ---------------------------------------------------------------------------
#define SW_OFF  2048
#define SA0_OFF 71680
#define SA1_OFF 106496
#define ROWPAD  272

__global__ __launch_bounds__(256, 1)
void dec_mma_kernel(const float* __restrict__ b1g,
                    const float* __restrict__ w3g,
                    const float* __restrict__ b3g,
                    float* __restrict__ outX,
                    float* __restrict__ outYr) {
    uint32_t sb = smem_u32(smemraw);
    float* sB1 = (float*)smemraw;
    float* sW3 = (float*)(smemraw + 1024);
    int tid = threadIdx.x, wid = tid >> 5, lane = tid & 31;
    int i = blockIdx.x;
    int tile0 = blockIdx.y * (NTILES / 64);   // 32 tiles per CTA

    // prefetch A tile0 (cp.async) before W staging
    {
        const unsigned char* src = g_abf + (size_t)tile0 * 32768;
        for (int idx = tid; idx < 2048; idx += 256) {
            int row = idx >> 4, c = idx & 15;
            cp_async16(sb + SA0_OFF + row * ROWPAD + c * 16, src + idx * 16);
        }
        CP_COMMIT();
    }
    // stage W' (padded rows) + b1/w3
    {
        const int4* src = (const int4*)(g_wbf + (size_t)i * 65536);
        for (int idx = tid; idx < 4096; idx += 256) {
            int row = idx >> 4, c = idx & 15;
            *(int4*)(smemraw + SW_OFF + row * ROWPAD + c * 16) = src[idx];
        }
        sB1[tid] = b1g[i * HID + tid];
        sW3[tid] = w3g[i * HID + tid];
    }
    float b3v = b3g[i];

    // per-lane ldmatrix address components
    int r8 = lane & 7, g = lane >> 3;
    // A: g0:(r,+0) g1:(r+8,+0) g2:(r,+16) g3:(r+8,+16)
    uint32_t aRow = (uint32_t)(wid * 16 + r8 + (g & 1) * 8);
    uint32_t aCol = (uint32_t)((g >> 1) * 16);
    uint32_t aBaseRel = aRow * ROWPAD + aCol;
    // B: g0:(ntpair rows 0-7,+0) g1:(same,+16) g2:(rows 8-15,+0) g3:(+16)
    uint32_t bRow = (uint32_t)((g >> 1) * 8 + r8);
    uint32_t bCol = (uint32_t)((g & 1) * 16);
    uint32_t bBaseRel = sb + SW_OFF + bRow * ROWPAD + bCol;

    int cq = (lane & 3) * 2, rq = lane >> 2;

    const int T = NTILES / 64;
    for (int j = 0; j < T; j++) {
        CP_WAIT0();
        __syncthreads();          // A[j] visible to all; prior tile reads done
        int buf = j & 1;
        if (j + 1 < T) {          // prefetch next tile into other buffer
            const unsigned char* src = g_abf + (size_t)(tile0 + j + 1) * 32768;
            uint32_t dstOff = buf ? SA0_OFF : SA1_OFF;
            for (int idx = tid; idx < 2048; idx += 256) {
                int row = idx >> 4, c = idx & 15;
                cp_async16(sb + dstOff + row * ROWPAD + c * 16, src + idx * 16);
            }
            CP_COMMIT();
        }

        uint32_t aBase = sb + (buf ? SA1_OFF : SA0_OFF) + aBaseRel;
        // load & hold A fragments: hi/lo x 4 k-steps
        uint32_t Ahi[4][4], Alo[4][4];
#pragma unroll
        for (int ks = 0; ks < 4; ks++) {
            ldsm_x4(aBase + ks * 32,       Ahi[ks][0], Ahi[ks][1], Ahi[ks][2], Ahi[ks][3]);
            ldsm_x4(aBase + 128 + ks * 32, Alo[ks][0], Alo[ks][1], Alo[ks][2], Alo[ks][3]);
        }

        float p0 = 0.f, p1 = 0.f;
#pragma unroll
        for (int nc = 0; nc < 4; nc++) {
            float acc[8][4];
#pragma unroll
            for (int t = 0; t < 8; t++)
#pragma unroll
                for (int q = 0; q < 4; q++) acc[t][q] = 0.f;

            uint32_t bNC = bBaseRel + (uint32_t)(nc * 64 * ROWPAD);
#pragma unroll
            for (int ks = 0; ks < 4; ks++) {
                uint32_t bh[16], bl[16];
#pragma unroll
                for (int tp = 0; tp < 4; tp++)
                    ldsm_x4(bNC + tp * 16 * ROWPAD + ks * 32,
                            bh[tp * 4], bh[tp * 4 + 1], bh[tp * 4 + 2], bh[tp * 4 + 3]);
#pragma unroll
                for (int nt = 0; nt < 8; nt++)
                    mma16816(acc[nt], Ahi[ks], bh[nt * 2], bh[nt * 2 + 1]);
#pragma unroll
                for (int nt = 0; nt < 8; nt++)
                    mma16816(acc[nt], Alo[ks], bh[nt * 2], bh[nt * 2 + 1]);
#pragma unroll
                for (int tp = 0; tp < 4; tp++)
                    ldsm_x4(bNC + tp * 16 * ROWPAD + 128 + ks * 32,
                            bl[tp * 4], bl[tp * 4 + 1], bl[tp * 4 + 2], bl[tp * 4 + 3]);
#pragma unroll
                for (int nt = 0; nt < 8; nt++)
                    mma16816(acc[nt], Ahi[ks], bl[nt * 2], bl[nt * 2 + 1]);
            }
            // fused relu + dot epilogue for this 64-col chunk
#pragma unroll
            for (int nt = 0; nt < 8; nt++) {
                int col = nc * 64 + nt * 8 + cq;
                float b1a = sB1[col], b1b = sB1[col + 1];
                float w3a = sW3[col], w3b = sW3[col + 1];
                p0 = fmaf(fmaxf(acc[nt][0] + b1a, 0.f), w3a, p0);
                p0 = fmaf(fmaxf(acc[nt][1] + b1b, 0.f), w3b, p0);
                p1 = fmaf(fmaxf(acc[nt][2] + b1a, 0.f), w3a, p1);
                p1 = fmaf(fmaxf(acc[nt][3] + b1b, 0.f), w3b, p1);
            }
        }
        // reduce across the 4 lanes sharing each row
#pragma unroll
        for (int off = 1; off <= 2; off <<= 1) {
            p0 += __shfl_xor_sync(0xFFFFFFFFu, p0, off);
            p1 += __shfl_xor_sync(0xFFFFFFFFu, p1, off);
        }
        if ((lane & 3) == 0) {
            size_t row0 = (size_t)(tile0 + j) * 128 + wid * 16 + rq;
            float o0 = p0 + b3v, o1 = p1 + b3v;
            outX[row0 * 64 + i] = o0;
            outX[(row0 + 8) * 64 + i] = o1;
            outYr[row0 * 128 + i] = o0;
            outYr[(row0 + 8) * 128 + i] = o1;
        }
    }
}

// ---------------------------------------------------------------------------
extern "C" void kernel_launch(void* const* d_in, const int* in_sizes, int n_in,
                              void* d_out, int out_size) {
    const float* x      = (const float*)d_in[0];
    const float* eps    = (const float*)d_in[1];
    const float* enc1_w = (const float*)d_in[2];
    const float* enc1_b = (const float*)d_in[3];
    const float* enc3_w = (const float*)d_in[4];
    const float* enc3_b = (const float*)d_in[5];
    const float* dec1_w = (const float*)d_in[6];
    const float* dec1_b = (const float*)d_in[7];
    const float* dec3_w = (const float*)d_in[8];
    const float* dec3_b = (const float*)d_in[9];
    const unsigned char* bmask = (const unsigned char*)d_in[10];
    (void)n_in; (void)in_sizes; (void)out_size;

    float* out   = (float*)d_out;
    float* outX  = out;
    float* outMu = out + (size_t)BATCH * DD;
    float* outLv = out + (size_t)2 * BATCH * DD;
    float* outYr = out + (size_t)3 * BATCH * DD;

    size_t sEnc = (size_t)(32768 + DD * HID + HID + 128) * sizeof(float);  // 198,144
    size_t sDec = 141312;
    cudaFuncSetAttribute(enc_fused_kernel, cudaFuncAttributeMaxDynamicSharedMemorySize, (int)sEnc);
    cudaFuncSetAttribute(dec_mma_kernel,   cudaFuncAttributeMaxDynamicSharedMemorySize, (int)sDec);

    mask_expand_kernel<<<1, 256>>>(bmask);
    wprep_kernel<<<DD, 256>>>(dec1_w);
    zero_yr_kernel<<<(BATCH * 16) / 256, 256>>>((float4*)outYr);
    enc_fused_kernel<<<BATCH / 64, 256, sEnc>>>(x, eps, enc1_w, enc1_b,
                                                enc3_w, enc3_b, outMu, outLv);
    dec_mma_kernel<<<dim3(DD, 64), 256, sDec>>>(dec1_b, dec3_w, dec3_b, outX, outYr);
}